// round 1
// baseline (speedup 1.0000x reference)
#include <cuda_runtime.h>
#include <cuda_bf16.h>
#include <math.h>

#define NNODES 32768
#define NEDGES 524288
#define NB     32
#define NPG    1024
#define CH     128
#define CIN    64

// ---------------- device scratch (no allocation allowed) ----------------
__device__ int   g_deg[NNODES];
__device__ int   g_off[NNODES + 1];
__device__ int   g_cur[NNODES];
__device__ int   g_srcbuf[NEDGES];
__device__ float g_dinv[NNODES];

__device__ float g_lin[NNODES * CH];
__device__ float g_agg[NNODES * CH];
__device__ float g_h  [NNODES * CH];
__device__ float g_s  [NNODES * CH];
__device__ float g_t  [NNODES * CH];

__device__ float g_x2  [NB * CH * CH];
__device__ float g_A2  [NB * CH * CH];
__device__ float g_An  [NB * CH * CH];
__device__ float g_dinv2[NB * CH];
__device__ float g_h2  [NB * CH * CH];
__device__ float g_tmp2[NB * CH * CH];
__device__ float g_y2  [NB * CH * CH];
__device__ float g_gpool[NB * CH];

__device__ float g_sum[CH], g_ss[CH], g_bnA[CH], g_bnB[CH];

// ---------------- small utility kernels ----------------
__global__ void k_zero_i(int* p, int n) {
    int i = blockIdx.x * 256 + threadIdx.x;
    if (i < n) p[i] = 0;
}
__global__ void k_zero_f(float* p, int n) {
    int i = blockIdx.x * 256 + threadIdx.x;
    if (i < n) p[i] = 0.f;
}
__global__ void k_zero_stats() {
    int c = threadIdx.x;
    g_sum[c] = 0.f; g_ss[c] = 0.f;
}

// ---------------- graph structure ----------------
__global__ void k_deg(const int* __restrict__ ei) {
    int e = blockIdx.x * 256 + threadIdx.x;
    if (e < NEDGES) atomicAdd(&g_deg[ei[NEDGES + e]], 1);
}

__global__ void k_scan() {
    __shared__ int sm[1024];
    __shared__ int carry;
    int t = threadIdx.x;
    if (t == 0) carry = 0;
    __syncthreads();
    for (int base = 0; base < NNODES; base += 1024) {
        int v = g_deg[base + t];
        sm[t] = v;
        __syncthreads();
        for (int d = 1; d < 1024; d <<= 1) {
            int x = (t >= d) ? sm[t - d] : 0;
            __syncthreads();
            sm[t] += x;
            __syncthreads();
        }
        int incl = sm[t];
        int excl = carry + incl - v;
        g_off[base + t] = excl;
        g_cur[base + t] = excl;
        g_dinv[base + t] = rsqrtf((float)v + 1.0f);
        __syncthreads();
        if (t == 1023) carry += sm[1023];
        __syncthreads();
    }
    if (t == 0) g_off[NNODES] = carry;
}

__global__ void k_fill(const int* __restrict__ ei) {
    int e = blockIdx.x * 256 + threadIdx.x;
    if (e < NEDGES) {
        int d = ei[NEDGES + e];
        int p = atomicAdd(&g_cur[d], 1);
        g_srcbuf[p] = ei[e];
    }
}

// ---------------- SGEMM: C[M,128] = op(A) @ B[K,128] (+bias) ----------------
// 128x128 tile, 8x8 microtile, 256 threads, K-step 8.
// TRANSA=false: A is [M,K] row-major.  TRANSA=true: A is [K,128] row-major (C = A^T B, M=128).
// kChunk: this block's K range is [blockIdx.y*kChunk, +kChunk). atomicOut for K-split.
template <bool TRANSA>
__global__ __launch_bounds__(256) void k_gemm(
    const float* __restrict__ A, const float* __restrict__ B,
    const float* __restrict__ bias, float* __restrict__ C,
    int K, int kChunk,
    long long sA, long long sB, long long sC, int atomicOut)
{
    __shared__ float As[8][128];
    __shared__ float Bs[8][128];
    A += (long long)blockIdx.z * sA;
    B += (long long)blockIdx.z * sB;
    C += (long long)blockIdx.z * sC;
    int m0 = blockIdx.x * 128;
    int t = threadIdx.x;
    int tx = t & 15, ty = t >> 4;
    float acc[8][8];
#pragma unroll
    for (int i = 0; i < 8; i++)
#pragma unroll
        for (int j = 0; j < 8; j++) acc[i][j] = 0.f;

    int kStart = blockIdx.y * kChunk;
    for (int k0 = kStart; k0 < kStart + kChunk; k0 += 8) {
        if (TRANSA) {
            int kk = t >> 5;
            int mq = (t & 31) << 2;
            float4 v = *reinterpret_cast<const float4*>(&A[(long long)(k0 + kk) * 128 + mq]);
            *reinterpret_cast<float4*>(&As[kk][mq]) = v;
        } else {
            int r  = t >> 1;
            int kq = (t & 1) << 2;
            float4 v = *reinterpret_cast<const float4*>(&A[(long long)(m0 + r) * K + k0 + kq]);
            As[kq + 0][r] = v.x; As[kq + 1][r] = v.y;
            As[kq + 2][r] = v.z; As[kq + 3][r] = v.w;
        }
        {
            int kk = t >> 5;
            int nq = (t & 31) << 2;
            float4 v = *reinterpret_cast<const float4*>(&B[(long long)(k0 + kk) * 128 + nq]);
            *reinterpret_cast<float4*>(&Bs[kk][nq]) = v;
        }
        __syncthreads();
#pragma unroll
        for (int kk = 0; kk < 8; kk++) {
            float a[8], b[8];
            *(float4*)&a[0] = *(const float4*)&As[kk][ty * 8];
            *(float4*)&a[4] = *(const float4*)&As[kk][ty * 8 + 4];
            *(float4*)&b[0] = *(const float4*)&Bs[kk][tx * 8];
            *(float4*)&b[4] = *(const float4*)&Bs[kk][tx * 8 + 4];
#pragma unroll
            for (int i = 0; i < 8; i++)
#pragma unroll
                for (int j = 0; j < 8; j++)
                    acc[i][j] = fmaf(a[i], b[j], acc[i][j]);
        }
        __syncthreads();
    }

#pragma unroll
    for (int i = 0; i < 8; i++) {
        long long row = m0 + ty * 8 + i;
#pragma unroll
        for (int j = 0; j < 8; j++) {
            int col = tx * 8 + j;
            float v = acc[i][j];
            if (bias) v += bias[col];
            if (atomicOut) atomicAdd(&C[row * 128 + col], v);
            else           C[row * 128 + col] = v;
        }
    }
}

// ---------------- sparse aggregation (CSR gather) ----------------
__global__ __launch_bounds__(128) void k_agg_gcn(
    const float* __restrict__ h, const float* __restrict__ bias, float* __restrict__ out)
{
    int i = blockIdx.x;
    int t = threadIdx.x;
    float di = g_dinv[i];
    float acc = di * h[(long long)i * CH + t];
    int e0 = g_off[i], e1 = g_off[i + 1];
    int e = e0;
    for (; e + 4 <= e1; e += 4) {
        int s0 = g_srcbuf[e], s1 = g_srcbuf[e + 1], s2 = g_srcbuf[e + 2], s3 = g_srcbuf[e + 3];
        float d0 = g_dinv[s0], d1 = g_dinv[s1], d2 = g_dinv[s2], d3 = g_dinv[s3];
        float h0 = h[(long long)s0 * CH + t];
        float h1 = h[(long long)s1 * CH + t];
        float h2 = h[(long long)s2 * CH + t];
        float h3 = h[(long long)s3 * CH + t];
        acc += d0 * h0 + d1 * h1 + d2 * h2 + d3 * h3;
    }
    for (; e < e1; e++) {
        int s = g_srcbuf[e];
        acc += g_dinv[s] * h[(long long)s * CH + t];
    }
    out[(long long)i * CH + t] = di * acc + bias[t];
}

__global__ __launch_bounds__(128) void k_agg_plain(
    const float* __restrict__ v, float* __restrict__ out)
{
    int i = blockIdx.x;
    int t = threadIdx.x;
    float acc = 0.f;
    int e0 = g_off[i], e1 = g_off[i + 1];
    int e = e0;
    for (; e + 4 <= e1; e += 4) {
        int s0 = g_srcbuf[e], s1 = g_srcbuf[e + 1], s2 = g_srcbuf[e + 2], s3 = g_srcbuf[e + 3];
        acc += v[(long long)s0 * CH + t] + v[(long long)s1 * CH + t]
             + v[(long long)s2 * CH + t] + v[(long long)s3 * CH + t];
    }
    for (; e < e1; e++) acc += v[(long long)g_srcbuf[e] * CH + t];
    out[(long long)i * CH + t] = acc;
}

// ---------------- batch-norm (training stats) + SiLU ----------------
__global__ void k_bnstats(const float* __restrict__ x, int nrows) {
    int c = threadIdx.x;   // 128
    float s = 0.f, q = 0.f;
    for (int r = blockIdx.x; r < nrows; r += gridDim.x) {
        float v = x[(long long)r * CH + c];
        s += v; q += v * v;
    }
    atomicAdd(&g_sum[c], s);
    atomicAdd(&g_ss[c], q);
}

__global__ void k_bnfin(const float* __restrict__ gw, const float* __restrict__ be, float inv_n) {
    int c = threadIdx.x;
    float m = g_sum[c] * inv_n;
    float v = g_ss[c] * inv_n - m * m;
    float sc = gw[c] * rsqrtf(v + 1e-5f);
    g_bnA[c] = sc;
    g_bnB[c] = be[c] - sc * m;
}

__global__ void k_bnapply(const float* __restrict__ x, const float* res, float* out, int total) {
    int i = blockIdx.x * 256 + threadIdx.x;
    if (i >= total) return;
    int c = i & 127;
    float y = g_bnA[c] * x[i] + g_bnB[c];
    y = y / (1.f + expf(-y));            // silu
    out[i] = (res ? res[i] : 0.f) + y;
}

// ---------------- row softmax over 128 ----------------
__global__ __launch_bounds__(128) void k_softmax(const float* __restrict__ in, float* __restrict__ out) {
    int r = blockIdx.x, t = threadIdx.x;
    __shared__ float red[128];
    float v = in[(long long)r * 128 + t];
    red[t] = v; __syncthreads();
    for (int s = 64; s; s >>= 1) { if (t < s) red[t] = fmaxf(red[t], red[t + s]); __syncthreads(); }
    float mx = red[0];
    __syncthreads();
    float e = expf(v - mx);
    red[t] = e; __syncthreads();
    for (int s = 64; s; s >>= 1) { if (t < s) red[t] += red[t + s]; __syncthreads(); }
    out[(long long)r * 128 + t] = e / red[0];
}

// ---------------- dense adjacency normalization ----------------
__global__ __launch_bounds__(128) void k_dinv2() {
    int row = blockIdx.x;   // b*128 + i  (4096 rows)
    int t = threadIdx.x;
    __shared__ float red[128];
    red[t] = g_A2[(long long)row * 128 + t];
    __syncthreads();
    for (int s = 64; s; s >>= 1) { if (t < s) red[t] += red[t + s]; __syncthreads(); }
    if (t == 0) g_dinv2[row] = rsqrtf(red[0] + 1.0f);
}

__global__ void k_an() {
    int idx = blockIdx.x * 256 + threadIdx.x;
    if (idx < NB * 128 * 128) {
        int j = idx & 127;
        int row = idx >> 7;       // b*128 + i
        int i = row & 127;
        int b = row >> 7;
        float v = g_A2[idx] + (i == j ? 1.f : 0.f);
        g_An[idx] = g_dinv2[row] * v * g_dinv2[b * 128 + j];
    }
}

// ---------------- final pooled mean + linear + log_softmax ----------------
__global__ __launch_bounds__(128) void k_colmean() {
    int b = blockIdx.x, t = threadIdx.x;
    float s = 0.f;
    for (int n = 0; n < 128; n++) s += g_h2[((long long)b * 128 + n) * 128 + t];
    g_gpool[b * 128 + t] = s * (1.f / 32.f);   // mean over K2=32 of s2^T h2, softmax rows sum to 1
}

__global__ __launch_bounds__(128) void k_head(
    const float* __restrict__ wl, const float* __restrict__ bl, float* __restrict__ out, int out_size)
{
    int b = blockIdx.x;
    int t = threadIdx.x;
    __shared__ float gv[128];
    __shared__ float lg[10];
    __shared__ float s_lse;
    gv[t] = g_gpool[b * 128 + t];
    __syncthreads();
    if (t < 10) {
        float s = bl[t];
        for (int k = 0; k < 128; k++) s += gv[k] * wl[k * 10 + t];
        lg[t] = s;
    }
    __syncthreads();
    if (t == 0) {
        float mx = -1e30f;
        for (int j = 0; j < 10; j++) mx = fmaxf(mx, lg[j]);
        float se = 0.f;
        for (int j = 0; j < 10; j++) se += expf(lg[j] - mx);
        s_lse = mx + logf(se);
    }
    __syncthreads();
    if (t < 10) {
        int o = b * 10 + t;
        if (o < out_size) out[o] = lg[t] - s_lse;
    }
}

// ---------------- host orchestration ----------------
extern "C" void kernel_launch(void* const* d_in, const int* in_sizes, int n_in,
                              void* d_out, int out_size) {
    const float* x    = (const float*)d_in[0];
    const int*   ei   = (const int*)  d_in[1];
    const float* w1a  = (const float*)d_in[4];
    const float* b1a  = (const float*)d_in[5];
    const float* g1a  = (const float*)d_in[6];
    const float* be1a = (const float*)d_in[7];
    const float* w1b  = (const float*)d_in[8];
    const float* b1b  = (const float*)d_in[9];
    const float* g1b  = (const float*)d_in[10];
    const float* be1b = (const float*)d_in[11];
    const float* wp1  = (const float*)d_in[12];
    const float* bp1  = (const float*)d_in[13];
    const float* w2a  = (const float*)d_in[14];
    const float* b2a  = (const float*)d_in[15];
    const float* g2a  = (const float*)d_in[16];
    const float* be2a = (const float*)d_in[17];
    const float* w2b  = (const float*)d_in[18];
    const float* b2b  = (const float*)d_in[19];
    const float* g2b  = (const float*)d_in[20];
    const float* be2b = (const float*)d_in[21];
    // d_in[22]=wp2, d_in[23]=bp2 are provably dead (softmax rows sum to 1)
    const float* wl   = (const float*)d_in[24];
    const float* bl   = (const float*)d_in[25];
    float* outp = (float*)d_out;

    float *p_deg_f; int *p_deg;
    float *p_lin, *p_agg, *p_h, *p_s, *p_t;
    float *p_x2, *p_A2, *p_h2, *p_tmp2, *p_y2;
    cudaGetSymbolAddress((void**)&p_deg,  g_deg);
    cudaGetSymbolAddress((void**)&p_lin,  g_lin);
    cudaGetSymbolAddress((void**)&p_agg,  g_agg);
    cudaGetSymbolAddress((void**)&p_h,    g_h);
    cudaGetSymbolAddress((void**)&p_s,    g_s);
    cudaGetSymbolAddress((void**)&p_t,    g_t);
    cudaGetSymbolAddress((void**)&p_x2,   g_x2);
    cudaGetSymbolAddress((void**)&p_A2,   g_A2);
    cudaGetSymbolAddress((void**)&p_h2,   g_h2);
    cudaGetSymbolAddress((void**)&p_tmp2, g_tmp2);
    cudaGetSymbolAddress((void**)&p_y2,   g_y2);
    (void)p_deg_f; (void)n_in; (void)in_sizes;

    const int NC = NNODES * CH;       // 4194304
    const int S2 = NB * CH * CH;      // 524288

    // --- graph structure (CSR + dinv) ---
    k_zero_i<<<NNODES / 256, 256>>>(p_deg, NNODES);
    k_deg <<<NEDGES / 256, 256>>>(ei);
    k_scan<<<1, 1024>>>();
    k_fill<<<NEDGES / 256, 256>>>(ei);

    // --- stack 1, block a ---
    k_gemm<false><<<dim3(256, 1, 1), 256>>>(x, w1a, nullptr, p_lin, CIN, CIN, 0, 0, 0, 0);
    k_agg_gcn<<<NNODES, 128>>>(p_lin, b1a, p_agg);
    k_zero_stats<<<1, 128>>>();
    k_bnstats<<<256, 128>>>(p_agg, NNODES);
    k_bnfin<<<1, 128>>>(g1a, be1a, 1.f / NNODES);
    k_bnapply<<<NC / 256, 256>>>(p_agg, nullptr, p_h, NC);

    // --- stack 1, block b (residual) ---
    k_gemm<false><<<dim3(256, 1, 1), 256>>>(p_h, w1b, nullptr, p_lin, CH, CH, 0, 0, 0, 0);
    k_agg_gcn<<<NNODES, 128>>>(p_lin, b1b, p_agg);
    k_zero_stats<<<1, 128>>>();
    k_bnstats<<<256, 128>>>(p_agg, NNODES);
    k_bnfin<<<1, 128>>>(g1b, be1b, 1.f / NNODES);
    k_bnapply<<<NC / 256, 256>>>(p_agg, p_h, p_h, NC);

    // --- pooling 1: s = softmax(gcn(h, wp1)) ---
    k_gemm<false><<<dim3(256, 1, 1), 256>>>(p_h, wp1, nullptr, p_lin, CH, CH, 0, 0, 0, 0);
    k_agg_gcn<<<NNODES, 128>>>(p_lin, bp1, p_agg);
    k_softmax<<<NNODES, 128>>>(p_agg, p_s);

    // t = A s (plain aggregation)
    k_agg_plain<<<NNODES, 128>>>(p_s, p_t);

    // x2 = s^T h, A2 = s^T t  (per batch; K=1024 split into 8 chunks, atomic accumulate)
    k_zero_f<<<S2 / 256, 256>>>(p_x2, S2);
    k_zero_f<<<S2 / 256, 256>>>(p_A2, S2);
    k_gemm<true><<<dim3(1, 8, NB), 256>>>(p_s, p_h, nullptr, p_x2, NPG, 128,
                                          (long long)NPG * CH, (long long)NPG * CH, (long long)CH * CH, 1);
    k_gemm<true><<<dim3(1, 8, NB), 256>>>(p_s, p_t, nullptr, p_A2, NPG, 128,
                                          (long long)NPG * CH, (long long)NPG * CH, (long long)CH * CH, 1);

    // --- dense normalized adjacency (shared by both dense layers) ---
    k_dinv2<<<NB * CH, 128>>>();
    k_an<<<S2 / 256, 256>>>();
    float* p_An; cudaGetSymbolAddress((void**)&p_An, g_An);

    // --- stack 2, block a ---
    k_gemm<false><<<dim3(32, 1, 1), 256>>>(p_x2, w2a, nullptr, p_tmp2, CH, CH, 0, 0, 0, 0);
    k_gemm<false><<<dim3(1, 1, NB), 256>>>(p_An, p_tmp2, b2a, p_y2, CH, CH,
                                           16384, 16384, 16384, 0);
    k_zero_stats<<<1, 128>>>();
    k_bnstats<<<64, 128>>>(p_y2, NB * CH);
    k_bnfin<<<1, 128>>>(g2a, be2a, 1.f / (NB * CH));
    k_bnapply<<<S2 / 256, 256>>>(p_y2, nullptr, p_h2, S2);

    // --- stack 2, block b (residual) ---
    k_gemm<false><<<dim3(32, 1, 1), 256>>>(p_h2, w2b, nullptr, p_tmp2, CH, CH, 0, 0, 0, 0);
    k_gemm<false><<<dim3(1, 1, NB), 256>>>(p_An, p_tmp2, b2b, p_y2, CH, CH,
                                           16384, 16384, 16384, 0);
    k_zero_stats<<<1, 128>>>();
    k_bnstats<<<64, 128>>>(p_y2, NB * CH);
    k_bnfin<<<1, 128>>>(g2b, be2b, 1.f / (NB * CH));
    k_bnapply<<<S2 / 256, 256>>>(p_y2, p_h2, p_h2, S2);

    // --- pooled mean (s2 collapses: softmax rows sum to 1) + head ---
    k_colmean<<<NB, 128>>>();
    k_head<<<NB, 128>>>(wl, bl, outp, out_size);

    // aux loss slot (and any padding) is exact zero
    if (out_size > NB * 10) {
        int tail = out_size - NB * 10;
        k_zero_f<<<(tail + 255) / 256, 256>>>(outp + NB * 10, tail);
    }
}

// round 2
// speedup vs baseline: 1.1692x; 1.1692x over previous
#include <cuda_runtime.h>
#include <cuda_bf16.h>
#include <math.h>

#define NNODES 32768
#define NEDGES 524288
#define NB     32
#define NPG    1024
#define CH     128
#define CIN    64

// ---------------- device scratch ----------------
__device__ int   g_deg[NNODES];
__device__ int   g_off[NNODES];
__device__ int   g_cur[NNODES];
__device__ int   g_total;
__device__ int   g_srcbuf[NEDGES];
__device__ float g_dinv[NNODES];

__device__ float g_aggx[NNODES * CIN];
__device__ float g_lin[NNODES * CH];
__device__ float g_y  [NNODES * CH];
__device__ float g_h  [NNODES * CH];
__device__ float g_s  [NNODES * CH];
__device__ float g_t  [NNODES * CH];

__device__ float g_xpart[4 * NB * CH * CH];
__device__ float g_apart[4 * NB * CH * CH];
__device__ float g_x2  [NB * CH * CH];
__device__ float g_A2  [NB * CH * CH];
__device__ float g_An  [NB * CH * CH];
__device__ float g_h2  [NB * CH * CH];
__device__ float g_tmp2[NB * CH * CH];
__device__ float g_y2  [NB * CH * CH];

__device__ float g_sum[CH], g_ss[CH];

// ---------------- utility ----------------
__global__ void k_zero_deg() {
    int i = blockIdx.x * 256 + threadIdx.x;
    if (i < NNODES) g_deg[i] = 0;
    if (i == 0) g_total = 0;
}
__global__ void k_zero_f(float* p, int n) {
    int i = blockIdx.x * 256 + threadIdx.x;
    if (i < n) p[i] = 0.f;
}

// ---------------- graph structure ----------------
__global__ void k_deg(const int* __restrict__ ei) {
    int e = blockIdx.x * 256 + threadIdx.x;
    if (e < NEDGES) atomicAdd(&g_deg[ei[NEDGES + e]], 1);
}

// warp-aggregated range allocation (order-free CSR, no global scan)
__global__ void k_alloc() {
    int t = threadIdx.x;
    int node = blockIdx.x * 1024 + t;
    int lane = t & 31;
    int deg = g_deg[node];
    int incl = deg;
#pragma unroll
    for (int d = 1; d < 32; d <<= 1) {
        int v = __shfl_up_sync(0xffffffffu, incl, d);
        if (lane >= d) incl += v;
    }
    int tot = __shfl_sync(0xffffffffu, incl, 31);
    int base = 0;
    if (lane == 31) base = atomicAdd(&g_total, tot);
    base = __shfl_sync(0xffffffffu, base, 31);
    int off = base + incl - deg;
    g_off[node] = off;
    g_cur[node] = off;
    g_dinv[node] = rsqrtf((float)deg + 1.0f);
}

__global__ void k_fill(const int* __restrict__ ei) {
    int e = blockIdx.x * 256 + threadIdx.x;
    if (e < NEDGES) {
        int d = ei[NEDGES + e];
        int p = atomicAdd(&g_cur[d], 1);
        g_srcbuf[p] = ei[e];
    }
}

// ---------------- big SGEMM: 128x128 tile, 8x8 micro, 256 thr ----------------
// TRANSA=false: C[M,128] = A[M,lda] @ B[K,128]; TRANSA=true: C[128,128] = A[K,128]^T @ B[K,128]
template <bool TRANSA>
__global__ __launch_bounds__(256) void k_gemm(
    const float* __restrict__ A, const float* __restrict__ B,
    const float* __restrict__ bias, float* __restrict__ C,
    int lda, int kChunk,
    long long sA, long long sB, long long sC, long long sCy, int zeroStats)
{
    __shared__ float As[8 * 132];
    __shared__ float Bs[8 * 128];
    int t = threadIdx.x;
    if (zeroStats && blockIdx.x == 0 && blockIdx.y == 0 && blockIdx.z == 0 && t < 128) {
        g_sum[t] = 0.f; g_ss[t] = 0.f;
    }
    A += (long long)blockIdx.z * sA;
    B += (long long)blockIdx.z * sB;
    C += (long long)blockIdx.z * sC + (long long)blockIdx.y * sCy;
    int m0 = blockIdx.x * 128;
    int tx = t & 15, ty = t >> 4;
    float acc[8][8];
#pragma unroll
    for (int i = 0; i < 8; i++)
#pragma unroll
        for (int j = 0; j < 8; j++) acc[i][j] = 0.f;

    int kStart = blockIdx.y * kChunk;
    for (int k0 = kStart; k0 < kStart + kChunk; k0 += 8) {
        if (TRANSA) {
            int kk = t >> 5;
            int mq = (t & 31) << 2;
            float4 v = *reinterpret_cast<const float4*>(&A[(long long)(k0 + kk) * 128 + mq]);
            *reinterpret_cast<float4*>(&As[kk * 132 + mq]) = v;
        } else {
            int r  = t >> 1;
            int kq = (t & 1) << 2;
            float4 v = *reinterpret_cast<const float4*>(&A[(long long)(m0 + r) * lda + k0 + kq]);
            As[(kq + 0) * 132 + r] = v.x; As[(kq + 1) * 132 + r] = v.y;
            As[(kq + 2) * 132 + r] = v.z; As[(kq + 3) * 132 + r] = v.w;
        }
        {
            int kk = t >> 5;
            int nq = (t & 31) << 2;
            float4 v = *reinterpret_cast<const float4*>(&B[(long long)(k0 + kk) * 128 + nq]);
            *reinterpret_cast<float4*>(&Bs[kk * 128 + nq]) = v;
        }
        __syncthreads();
#pragma unroll
        for (int kk = 0; kk < 8; kk++) {
            float a[8], b[8];
            *(float4*)&a[0] = *(const float4*)&As[kk * 132 + ty * 8];
            *(float4*)&a[4] = *(const float4*)&As[kk * 132 + ty * 8 + 4];
            *(float4*)&b[0] = *(const float4*)&Bs[kk * 128 + tx * 8];
            *(float4*)&b[4] = *(const float4*)&Bs[kk * 128 + tx * 8 + 4];
#pragma unroll
            for (int i = 0; i < 8; i++)
#pragma unroll
                for (int j = 0; j < 8; j++)
                    acc[i][j] = fmaf(a[i], b[j], acc[i][j]);
        }
        __syncthreads();
    }

#pragma unroll
    for (int i = 0; i < 8; i++) {
        long long row = m0 + ty * 8 + i;
#pragma unroll
        for (int j = 0; j < 8; j++) {
            int col = tx * 8 + j;
            float v = acc[i][j];
            if (bias) v += bias[col];
            C[row * 128 + col] = v;
        }
    }
}

// ---------------- small SGEMM: 64x64 tile, 4x4 micro, 256 thr ----------------
__global__ __launch_bounds__(256) void k_gemm64(
    const float* __restrict__ A, const float* __restrict__ B,
    const float* __restrict__ bias, float* __restrict__ C,
    int K, long long sA, long long sB, long long sC, int zeroStats)
{
    __shared__ float As[16 * 68];
    __shared__ float Bs[16 * 64];
    int t = threadIdx.x;
    if (zeroStats && blockIdx.x == 0 && blockIdx.y == 0 && blockIdx.z == 0 && t < 128) {
        g_sum[t] = 0.f; g_ss[t] = 0.f;
    }
    A += (long long)blockIdx.z * sA;
    B += (long long)blockIdx.z * sB;
    C += (long long)blockIdx.z * sC;
    int m0 = blockIdx.x * 64;
    int n0 = blockIdx.y * 64;
    int tx = t & 15, ty = t >> 4;
    float acc[4][4];
#pragma unroll
    for (int i = 0; i < 4; i++)
#pragma unroll
        for (int j = 0; j < 4; j++) acc[i][j] = 0.f;

    for (int k0 = 0; k0 < K; k0 += 16) {
        {
            int r  = t >> 2;
            int kq = (t & 3) << 2;
            float4 v = *reinterpret_cast<const float4*>(&A[(long long)(m0 + r) * 128 + k0 + kq]);
            As[(kq + 0) * 68 + r] = v.x; As[(kq + 1) * 68 + r] = v.y;
            As[(kq + 2) * 68 + r] = v.z; As[(kq + 3) * 68 + r] = v.w;
        }
        {
            int kk = t >> 4;
            int nq = (t & 15) << 2;
            float4 v = *reinterpret_cast<const float4*>(&B[(long long)(k0 + kk) * 128 + n0 + nq]);
            *reinterpret_cast<float4*>(&Bs[kk * 64 + nq]) = v;
        }
        __syncthreads();
#pragma unroll
        for (int kk = 0; kk < 16; kk++) {
            float a[4], b[4];
#pragma unroll
            for (int i = 0; i < 4; i++) a[i] = As[kk * 68 + ty * 4 + i];
            *(float4*)&b[0] = *(const float4*)&Bs[kk * 64 + tx * 4];
#pragma unroll
            for (int i = 0; i < 4; i++)
#pragma unroll
                for (int j = 0; j < 4; j++)
                    acc[i][j] = fmaf(a[i], b[j], acc[i][j]);
        }
        __syncthreads();
    }
#pragma unroll
    for (int i = 0; i < 4; i++) {
        long long row = m0 + ty * 4 + i;
#pragma unroll
        for (int j = 0; j < 4; j++) {
            int col = n0 + tx * 4 + j;
            float v = acc[i][j];
            if (bias) v += bias[col];
            C[row * 128 + col] = v;
        }
    }
}

// ---------------- sparse aggregation (CSR gather), multi-node blocks ----------------
template <int CHN, bool SOFTMAX, bool ZERO>
__global__ __launch_bounds__(256) void k_agg_gcn(
    const float* __restrict__ in, const float* __restrict__ bias, float* __restrict__ out)
{
    int t = threadIdx.x;
    if (ZERO && blockIdx.x == 0 && t < 128) { g_sum[t] = 0.f; g_ss[t] = 0.f; }
    const int NPB = 256 / CHN;
    int local = t / CHN;
    int c = t % CHN;
    int i = blockIdx.x * NPB + local;
    float di = g_dinv[i];
    float acc = di * in[(size_t)i * CHN + c];
    int e = g_off[i];
    int e1 = e + g_deg[i];
    for (; e + 4 <= e1; e += 4) {
        int s0 = g_srcbuf[e], s1 = g_srcbuf[e + 1], s2 = g_srcbuf[e + 2], s3 = g_srcbuf[e + 3];
        float d0 = g_dinv[s0], d1 = g_dinv[s1], d2 = g_dinv[s2], d3 = g_dinv[s3];
        float h0 = in[(size_t)s0 * CHN + c];
        float h1 = in[(size_t)s1 * CHN + c];
        float h2 = in[(size_t)s2 * CHN + c];
        float h3 = in[(size_t)s3 * CHN + c];
        acc += d0 * h0 + d1 * h1 + d2 * h2 + d3 * h3;
    }
    for (; e < e1; e++) {
        int s = g_srcbuf[e];
        acc += g_dinv[s] * in[(size_t)s * CHN + c];
    }
    float v = di * acc + (bias ? bias[c] : 0.f);
    if (!SOFTMAX) {
        out[(size_t)i * CHN + c] = v;
    } else {
        __shared__ float red[256];
        red[t] = v; __syncthreads();
#pragma unroll
        for (int s = 64; s; s >>= 1) {
            if (c < s) red[t] = fmaxf(red[t], red[t + s]);
            __syncthreads();
        }
        float mx = red[local * 128];
        __syncthreads();
        float ex = expf(v - mx);
        red[t] = ex; __syncthreads();
#pragma unroll
        for (int s = 64; s; s >>= 1) {
            if (c < s) red[t] += red[t + s];
            __syncthreads();
        }
        out[(size_t)i * CHN + c] = ex / red[local * 128];
    }
}

__global__ __launch_bounds__(256) void k_agg_plain(
    const float* __restrict__ in, float* __restrict__ out)
{
    int t = threadIdx.x;
    int local = t >> 7;
    int c = t & 127;
    int i = blockIdx.x * 2 + local;
    float acc = 0.f;
    int e = g_off[i];
    int e1 = e + g_deg[i];
    for (; e + 4 <= e1; e += 4) {
        int s0 = g_srcbuf[e], s1 = g_srcbuf[e + 1], s2 = g_srcbuf[e + 2], s3 = g_srcbuf[e + 3];
        acc += in[(size_t)s0 * CH + c] + in[(size_t)s1 * CH + c]
             + in[(size_t)s2 * CH + c] + in[(size_t)s3 * CH + c];
    }
    for (; e < e1; e++) acc += in[(size_t)g_srcbuf[e] * CH + c];
    out[(size_t)i * CH + c] = acc;
}

// ---------------- batch-norm stats + apply (fin inlined) ----------------
__global__ __launch_bounds__(128) void k_bnstats(const float* __restrict__ x, int nrows) {
    int c = threadIdx.x;
    float s = 0.f, q = 0.f;
    for (int r = blockIdx.x; r < nrows; r += gridDim.x) {
        float v = x[(long long)r * CH + c];
        s += v; q += v * v;
    }
    atomicAdd(&g_sum[c], s);
    atomicAdd(&g_ss[c], q);
}

__global__ __launch_bounds__(256) void k_bnapply4(
    const float4* __restrict__ x, const float4* __restrict__ res, float4* __restrict__ out,
    int n4, const float* __restrict__ gw, const float* __restrict__ be, float inv_n)
{
    __shared__ float sA[128], sB[128];
    int t = threadIdx.x;
    if (t < 128) {
        float m = g_sum[t] * inv_n;
        float v = g_ss[t] * inv_n - m * m;
        float sc = gw[t] * rsqrtf(v + 1e-5f);
        sA[t] = sc;
        sB[t] = be[t] - sc * m;
    }
    __syncthreads();
    int i = blockIdx.x * 256 + t;
    if (i >= n4) return;
    int c0 = (i & 31) << 2;
    float4 xv = x[i];
    float4 o;
    float y;
    y = sA[c0 + 0] * xv.x + sB[c0 + 0]; o.x = y / (1.f + expf(-y));
    y = sA[c0 + 1] * xv.y + sB[c0 + 1]; o.y = y / (1.f + expf(-y));
    y = sA[c0 + 2] * xv.z + sB[c0 + 2]; o.z = y / (1.f + expf(-y));
    y = sA[c0 + 3] * xv.w + sB[c0 + 3]; o.w = y / (1.f + expf(-y));
    if (res) {
        float4 r = res[i];
        o.x += r.x; o.y += r.y; o.z += r.z; o.w += r.w;
    }
    out[i] = o;
}

// ---------------- partial reduce + dinv2 + An (per batch) ----------------
__global__ __launch_bounds__(256) void k_reduce_an() {
    int b = blockIdx.x;
    int t = threadIdx.x;
    const int PS = NB * CH * CH;
    const int BO = b * CH * CH;
    __shared__ float sd[128];
    // x2 = sum of partials
    for (int idx = t; idx < CH * CH; idx += 256) {
        float s = g_xpart[0 * PS + BO + idx] + g_xpart[1 * PS + BO + idx]
                + g_xpart[2 * PS + BO + idx] + g_xpart[3 * PS + BO + idx];
        g_x2[BO + idx] = s;
    }
    // A2 = sum of partials, with per-row sums
    int w = t >> 5, lane = t & 31;
    for (int r = w; r < 128; r += 8) {
        float rsum = 0.f;
#pragma unroll
        for (int q = 0; q < 4; q++) {
            int idx = r * 128 + lane + q * 32;
            float s = g_apart[0 * PS + BO + idx] + g_apart[1 * PS + BO + idx]
                    + g_apart[2 * PS + BO + idx] + g_apart[3 * PS + BO + idx];
            g_A2[BO + idx] = s;
            rsum += s;
        }
#pragma unroll
        for (int o = 16; o; o >>= 1) rsum += __shfl_down_sync(0xffffffffu, rsum, o);
        if (lane == 0) sd[r] = rsqrtf(rsum + 1.0f);
    }
    __syncthreads();
    // An = dinv (A2 + I) dinv
    for (int idx = t; idx < CH * CH; idx += 256) {
        int i = idx >> 7, j = idx & 127;
        float v = g_A2[BO + idx] + (i == j ? 1.f : 0.f);
        g_An[BO + idx] = sd[i] * v * sd[j];
    }
}

// ---------------- pooled column-mean + linear head + log_softmax ----------------
__global__ __launch_bounds__(128) void k_head(
    const float* __restrict__ wl, const float* __restrict__ bl, float* __restrict__ out, int out_size)
{
    int b = blockIdx.x;
    int t = threadIdx.x;
    __shared__ float gv[128];
    __shared__ float lg[10];
    __shared__ float s_lse;
    float s = 0.f;
    for (int n = 0; n < 128; n++) s += g_h2[((long long)b * 128 + n) * 128 + t];
    gv[t] = s * (1.f / 32.f);
    __syncthreads();
    if (t < 10) {
        float a = bl[t];
        for (int k = 0; k < 128; k++) a += gv[k] * wl[k * 10 + t];
        lg[t] = a;
    }
    __syncthreads();
    if (t == 0) {
        float mx = -1e30f;
        for (int j = 0; j < 10; j++) mx = fmaxf(mx, lg[j]);
        float se = 0.f;
        for (int j = 0; j < 10; j++) se += expf(lg[j] - mx);
        s_lse = mx + logf(se);
    }
    __syncthreads();
    if (t < 10) {
        int o = b * 10 + t;
        if (o < out_size) out[o] = lg[t] - s_lse;
    }
}

// ---------------- host orchestration ----------------
extern "C" void kernel_launch(void* const* d_in, const int* in_sizes, int n_in,
                              void* d_out, int out_size) {
    const float* x    = (const float*)d_in[0];
    const int*   ei   = (const int*)  d_in[1];
    const float* w1a  = (const float*)d_in[4];
    const float* b1a  = (const float*)d_in[5];
    const float* g1a  = (const float*)d_in[6];
    const float* be1a = (const float*)d_in[7];
    const float* w1b  = (const float*)d_in[8];
    const float* b1b  = (const float*)d_in[9];
    const float* g1b  = (const float*)d_in[10];
    const float* be1b = (const float*)d_in[11];
    const float* wp1  = (const float*)d_in[12];
    const float* bp1  = (const float*)d_in[13];
    const float* w2a  = (const float*)d_in[14];
    const float* b2a  = (const float*)d_in[15];
    const float* g2a  = (const float*)d_in[16];
    const float* be2a = (const float*)d_in[17];
    const float* w2b  = (const float*)d_in[18];
    const float* b2b  = (const float*)d_in[19];
    const float* g2b  = (const float*)d_in[20];
    const float* be2b = (const float*)d_in[21];
    // d_in[22]=wp2, d_in[23]=bp2 dead (softmax rows sum to 1)
    const float* wl   = (const float*)d_in[24];
    const float* bl   = (const float*)d_in[25];
    float* outp = (float*)d_out;
    (void)n_in; (void)in_sizes;

    float *p_aggx, *p_lin, *p_y, *p_h, *p_s, *p_t;
    float *p_xpart, *p_apart, *p_x2, *p_An, *p_h2, *p_tmp2, *p_y2;
    cudaGetSymbolAddress((void**)&p_aggx,  g_aggx);
    cudaGetSymbolAddress((void**)&p_lin,   g_lin);
    cudaGetSymbolAddress((void**)&p_y,     g_y);
    cudaGetSymbolAddress((void**)&p_h,     g_h);
    cudaGetSymbolAddress((void**)&p_s,     g_s);
    cudaGetSymbolAddress((void**)&p_t,     g_t);
    cudaGetSymbolAddress((void**)&p_xpart, g_xpart);
    cudaGetSymbolAddress((void**)&p_apart, g_apart);
    cudaGetSymbolAddress((void**)&p_x2,    g_x2);
    cudaGetSymbolAddress((void**)&p_An,    g_An);
    cudaGetSymbolAddress((void**)&p_h2,    g_h2);
    cudaGetSymbolAddress((void**)&p_tmp2,  g_tmp2);
    cudaGetSymbolAddress((void**)&p_y2,    g_y2);

    const int NC = NNODES * CH;     // 4194304
    const int S2 = NB * CH * CH;    // 524288

    // --- graph structure ---
    k_zero_deg<<<NNODES / 256, 256>>>();
    k_deg  <<<NEDGES / 256, 256>>>(ei);
    k_alloc<<<NNODES / 1024, 1024>>>();
    k_fill <<<NEDGES / 256, 256>>>(ei);

    // --- stack 1, layer a: agg(x) first (64ch), then GEMM 64->128 with bias ---
    k_agg_gcn<64, false, false><<<NNODES / 4, 256>>>(x, nullptr, p_aggx);
    k_gemm<false><<<dim3(256, 1, 1), 256>>>(p_aggx, w1a, b1a, p_y, 64, 64, 0, 0, 0, 0, 1);
    k_bnstats<<<256, 128>>>(p_y, NNODES);
    k_bnapply4<<<NC / 1024, 256>>>((const float4*)p_y, nullptr, (float4*)p_h, NC / 4, g1a, be1a, 1.f / NNODES);

    // --- stack 1, layer b (residual) ---
    k_gemm<false><<<dim3(256, 1, 1), 256>>>(p_h, w1b, nullptr, p_lin, 128, 128, 0, 0, 0, 0, 0);
    k_agg_gcn<128, false, true><<<NNODES / 2, 256>>>(p_lin, b1b, p_y);
    k_bnstats<<<256, 128>>>(p_y, NNODES);
    k_bnapply4<<<NC / 1024, 256>>>((const float4*)p_y, (const float4*)p_h, (float4*)p_h, NC / 4, g1b, be1b, 1.f / NNODES);

    // --- pooling 1: s = softmax(gcn(h, wp1)) fused; t = A s ---
    k_gemm<false><<<dim3(256, 1, 1), 256>>>(p_h, wp1, nullptr, p_lin, 128, 128, 0, 0, 0, 0, 0);
    k_agg_gcn<128, true, false><<<NNODES / 2, 256>>>(p_lin, bp1, p_s);
    k_agg_plain<<<NNODES / 2, 256>>>(p_s, p_t);

    // --- pooled einsums: K-split x4 into partial buffers (no atomics) ---
    k_gemm<true><<<dim3(1, 4, NB), 256>>>(p_s, p_h, nullptr, p_xpart, 128, 256,
                                          (long long)NPG * CH, (long long)NPG * CH,
                                          (long long)CH * CH, (long long)NB * CH * CH, 0);
    k_gemm<true><<<dim3(1, 4, NB), 256>>>(p_s, p_t, nullptr, p_apart, 128, 256,
                                          (long long)NPG * CH, (long long)NPG * CH,
                                          (long long)CH * CH, (long long)NB * CH * CH, 0);
    k_reduce_an<<<NB, 256>>>();

    // --- stack 2, layer a ---
    k_gemm64<<<dim3(64, 2, 1), 256>>>(p_x2, w2a, nullptr, p_tmp2, 128, 0, 0, 0, 0);
    k_gemm64<<<dim3(2, 2, NB), 256>>>(p_An, p_tmp2, b2a, p_y2, 128, 16384, 16384, 16384, 1);
    k_bnstats<<<64, 128>>>(p_y2, NB * CH);
    k_bnapply4<<<S2 / 1024, 256>>>((const float4*)p_y2, nullptr, (float4*)p_h2, S2 / 4, g2a, be2a, 1.f / (NB * CH));

    // --- stack 2, layer b (residual) ---
    k_gemm64<<<dim3(64, 2, 1), 256>>>(p_h2, w2b, nullptr, p_tmp2, 128, 0, 0, 0, 0);
    k_gemm64<<<dim3(2, 2, NB), 256>>>(p_An, p_tmp2, b2b, p_y2, 128, 16384, 16384, 16384, 1);
    k_bnstats<<<64, 128>>>(p_y2, NB * CH);
    k_bnapply4<<<S2 / 1024, 256>>>((const float4*)p_y2, (const float4*)p_h2, (float4*)p_h2, S2 / 4, g2b, be2b, 1.f / (NB * CH));

    // --- head ---
    k_head<<<NB, 128>>>(wl, bl, outp, out_size);

    if (out_size > NB * 10) {
        int tail = out_size - NB * 10;
        k_zero_f<<<(tail + 255) / 256, 256>>>(outp + NB * 10, tail);
    }
}

// round 4
// speedup vs baseline: 1.1886x; 1.0166x over previous
#include <cuda_runtime.h>
#include <cuda_bf16.h>
#include <math.h>

#define NNODES 32768
#define NEDGES 524288
#define NB     32
#define NPG    1024
#define CH     128
#define CIN    64

// ---------------- device scratch ----------------
__device__ int   g_deg[NNODES];
__device__ int   g_off[NNODES];
__device__ int   g_cur[NNODES];
__device__ int   g_total;
__device__ int   g_srcbuf[NEDGES];
__device__ float g_dinv[NNODES];

__device__ float g_aggx[NNODES * CIN];
__device__ float g_lin[NNODES * CH];
__device__ float g_y  [NNODES * CH];
__device__ float g_h  [NNODES * CH];
__device__ float g_s  [NNODES * CH];
__device__ float g_t  [NNODES * CH];

__device__ float g_xpart[4 * NB * CH * CH];
__device__ float g_apart[4 * NB * CH * CH];
__device__ float g_x2  [NB * CH * CH];
__device__ float g_A2  [NB * CH * CH];
__device__ float g_An  [NB * CH * CH];
__device__ float g_h2  [NB * CH * CH];
__device__ float g_tmp2[NB * CH * CH];
__device__ float g_y2  [NB * CH * CH];

__device__ float g_sum[CH], g_ss[CH];

// packed fp32x2 FMA: d = a*b + d, lanewise on 2 floats in a 64-bit reg.
// Base sm_100+ PTX (NOT an 'a'-variant feature like tcgen05).
__device__ __forceinline__ void ffma2(unsigned long long& d, unsigned long long a, unsigned long long b) {
    asm("fma.rn.f32x2 %0, %1, %2, %0;" : "+l"(d) : "l"(a), "l"(b));
}
__device__ __forceinline__ unsigned long long dup_f32(float v) {
    unsigned long long r;
    asm("mov.b64 %0, {%1, %1};" : "=l"(r) : "f"(v));
    return r;
}

// ---------------- utility ----------------
__global__ void k_zero_deg() {
    int i = blockIdx.x * 256 + threadIdx.x;
    if (i < NNODES) g_deg[i] = 0;
    if (i == 0) g_total = 0;
}
__global__ void k_zero_f(float* p, int n) {
    int i = blockIdx.x * 256 + threadIdx.x;
    if (i < n) p[i] = 0.f;
}

// ---------------- graph structure ----------------
__global__ void k_deg(const int* __restrict__ ei) {
    int e = blockIdx.x * 256 + threadIdx.x;
    if (e < NEDGES) atomicAdd(&g_deg[ei[NEDGES + e]], 1);
}

__global__ void k_alloc() {
    int t = threadIdx.x;
    int node = blockIdx.x * 1024 + t;
    int lane = t & 31;
    int deg = g_deg[node];
    int incl = deg;
#pragma unroll
    for (int d = 1; d < 32; d <<= 1) {
        int v = __shfl_up_sync(0xffffffffu, incl, d);
        if (lane >= d) incl += v;
    }
    int tot = __shfl_sync(0xffffffffu, incl, 31);
    int base = 0;
    if (lane == 31) base = atomicAdd(&g_total, tot);
    base = __shfl_sync(0xffffffffu, base, 31);
    int off = base + incl - deg;
    g_off[node] = off;
    g_cur[node] = off;
    g_dinv[node] = rsqrtf((float)deg + 1.0f);
}

__global__ void k_fill(const int* __restrict__ ei) {
    int e = blockIdx.x * 256 + threadIdx.x;
    if (e < NEDGES) {
        int d = ei[NEDGES + e];
        int p = atomicAdd(&g_cur[d], 1);
        g_srcbuf[p] = ei[e];
    }
}

// ---------------- big SGEMM: 128x128 tile, 8x8 micro, 256 thr, FFMA2 inner ----------------
// TRANSA=false: C[M,128] = A[M,lda] @ B[K,128]; TRANSA=true: C[128,128] = A[K,128]^T @ B[K,128]
template <bool TRANSA>
__global__ __launch_bounds__(256) void k_gemm(
    const float* __restrict__ A, const float* __restrict__ B,
    const float* __restrict__ bias, float* __restrict__ C,
    int lda, int kChunk,
    long long sA, long long sB, long long sC, long long sCy, int zeroStats)
{
    __shared__ __align__(16) float As[8 * 132];
    __shared__ __align__(16) float Bs[8 * 128];
    int t = threadIdx.x;
    if (zeroStats && blockIdx.x == 0 && blockIdx.y == 0 && blockIdx.z == 0 && t < 128) {
        g_sum[t] = 0.f; g_ss[t] = 0.f;
    }
    A += (long long)blockIdx.z * sA;
    B += (long long)blockIdx.z * sB;
    C += (long long)blockIdx.z * sC + (long long)blockIdx.y * sCy;
    int m0 = blockIdx.x * 128;
    int tx = t & 15, ty = t >> 4;
    unsigned long long acc2[8][4];
#pragma unroll
    for (int i = 0; i < 8; i++)
#pragma unroll
        for (int j = 0; j < 4; j++) acc2[i][j] = 0ull;

    int kStart = blockIdx.y * kChunk;
    for (int k0 = kStart; k0 < kStart + kChunk; k0 += 8) {
        if (TRANSA) {
            int kk = t >> 5;
            int mq = (t & 31) << 2;
            float4 v = *reinterpret_cast<const float4*>(&A[(long long)(k0 + kk) * 128 + mq]);
            *reinterpret_cast<float4*>(&As[kk * 132 + mq]) = v;
        } else {
            int r  = t >> 1;
            int kq = (t & 1) << 2;
            float4 v = *reinterpret_cast<const float4*>(&A[(long long)(m0 + r) * lda + k0 + kq]);
            As[(kq + 0) * 132 + r] = v.x; As[(kq + 1) * 132 + r] = v.y;
            As[(kq + 2) * 132 + r] = v.z; As[(kq + 3) * 132 + r] = v.w;
        }
        {
            int kk = t >> 5;
            int nq = (t & 31) << 2;
            float4 v = *reinterpret_cast<const float4*>(&B[(long long)(k0 + kk) * 128 + nq]);
            *reinterpret_cast<float4*>(&Bs[kk * 128 + nq]) = v;
        }
        __syncthreads();
#pragma unroll
        for (int kk = 0; kk < 8; kk++) {
            float a[8];
            unsigned long long b2[4];
            *(float4*)&a[0] = *(const float4*)&As[kk * 132 + ty * 8];
            *(float4*)&a[4] = *(const float4*)&As[kk * 132 + ty * 8 + 4];
            const unsigned long long* Bp =
                reinterpret_cast<const unsigned long long*>(&Bs[kk * 128 + tx * 8]);
            b2[0] = Bp[0]; b2[1] = Bp[1]; b2[2] = Bp[2]; b2[3] = Bp[3];
#pragma unroll
            for (int i = 0; i < 8; i++) {
                unsigned long long ad = dup_f32(a[i]);
#pragma unroll
                for (int j = 0; j < 4; j++) ffma2(acc2[i][j], ad, b2[j]);
            }
        }
        __syncthreads();
    }

#pragma unroll
    for (int i = 0; i < 8; i++) {
        long long row = m0 + ty * 8 + i;
        const float* af = reinterpret_cast<const float*>(&acc2[i][0]);
#pragma unroll
        for (int j = 0; j < 8; j++) {
            int col = tx * 8 + j;
            float v = af[j];
            if (bias) v += bias[col];
            C[row * 128 + col] = v;
        }
    }
}

// ---------------- small SGEMM: 64x64 tile, 4x4 micro, 256 thr, FFMA2 inner ----------------
__global__ __launch_bounds__(256) void k_gemm64(
    const float* __restrict__ A, const float* __restrict__ B,
    const float* __restrict__ bias, float* __restrict__ C,
    int K, long long sA, long long sB, long long sC, int zeroStats)
{
    __shared__ __align__(16) float As[16 * 68];
    __shared__ __align__(16) float Bs[16 * 64];
    int t = threadIdx.x;
    if (zeroStats && blockIdx.x == 0 && blockIdx.y == 0 && blockIdx.z == 0 && t < 128) {
        g_sum[t] = 0.f; g_ss[t] = 0.f;
    }
    A += (long long)blockIdx.z * sA;
    B += (long long)blockIdx.z * sB;
    C += (long long)blockIdx.z * sC;
    int m0 = blockIdx.x * 64;
    int n0 = blockIdx.y * 64;
    int tx = t & 15, ty = t >> 4;
    unsigned long long acc2[4][2];
#pragma unroll
    for (int i = 0; i < 4; i++) { acc2[i][0] = 0ull; acc2[i][1] = 0ull; }

    for (int k0 = 0; k0 < K; k0 += 16) {
        {
            int r  = t >> 2;
            int kq = (t & 3) << 2;
            float4 v = *reinterpret_cast<const float4*>(&A[(long long)(m0 + r) * 128 + k0 + kq]);
            As[(kq + 0) * 68 + r] = v.x; As[(kq + 1) * 68 + r] = v.y;
            As[(kq + 2) * 68 + r] = v.z; As[(kq + 3) * 68 + r] = v.w;
        }
        {
            int kk = t >> 4;
            int nq = (t & 15) << 2;
            float4 v = *reinterpret_cast<const float4*>(&B[(long long)(k0 + kk) * 128 + n0 + nq]);
            *reinterpret_cast<float4*>(&Bs[kk * 64 + nq]) = v;
        }
        __syncthreads();
#pragma unroll
        for (int kk = 0; kk < 16; kk++) {
            float a[4];
            unsigned long long b2[2];
#pragma unroll
            for (int i = 0; i < 4; i++) a[i] = As[kk * 68 + ty * 4 + i];
            const unsigned long long* Bp =
                reinterpret_cast<const unsigned long long*>(&Bs[kk * 64 + tx * 4]);
            b2[0] = Bp[0]; b2[1] = Bp[1];
#pragma unroll
            for (int i = 0; i < 4; i++) {
                unsigned long long ad = dup_f32(a[i]);
                ffma2(acc2[i][0], ad, b2[0]);
                ffma2(acc2[i][1], ad, b2[1]);
            }
        }
        __syncthreads();
    }
#pragma unroll
    for (int i = 0; i < 4; i++) {
        long long row = m0 + ty * 4 + i;
        const float* af = reinterpret_cast<const float*>(&acc2[i][0]);
#pragma unroll
        for (int j = 0; j < 4; j++) {
            int col = n0 + tx * 4 + j;
            float v = af[j];
            if (bias) v += bias[col];
            C[row * 128 + col] = v;
        }
    }
}

// ---------------- sparse aggregation (CSR gather), multi-node blocks ----------------
template <int CHN, bool SOFTMAX, bool ZERO>
__global__ __launch_bounds__(256) void k_agg_gcn(
    const float* __restrict__ in, const float* __restrict__ bias, float* __restrict__ out)
{
    int t = threadIdx.x;
    if (ZERO && blockIdx.x == 0 && t < 128) { g_sum[t] = 0.f; g_ss[t] = 0.f; }
    const int NPB = 256 / CHN;
    int local = t / CHN;
    int c = t % CHN;
    int i = blockIdx.x * NPB + local;
    float di = g_dinv[i];
    float acc = di * in[(size_t)i * CHN + c];
    int e = g_off[i];
    int e1 = e + g_deg[i];
    for (; e + 4 <= e1; e += 4) {
        int s0 = g_srcbuf[e], s1 = g_srcbuf[e + 1], s2 = g_srcbuf[e + 2], s3 = g_srcbuf[e + 3];
        float d0 = g_dinv[s0], d1 = g_dinv[s1], d2 = g_dinv[s2], d3 = g_dinv[s3];
        float h0 = in[(size_t)s0 * CHN + c];
        float h1 = in[(size_t)s1 * CHN + c];
        float h2 = in[(size_t)s2 * CHN + c];
        float h3 = in[(size_t)s3 * CHN + c];
        acc += d0 * h0 + d1 * h1 + d2 * h2 + d3 * h3;
    }
    for (; e < e1; e++) {
        int s = g_srcbuf[e];
        acc += g_dinv[s] * in[(size_t)s * CHN + c];
    }
    float v = di * acc + (bias ? bias[c] : 0.f);
    if (!SOFTMAX) {
        out[(size_t)i * CHN + c] = v;
    } else {
        __shared__ float red[256];
        red[t] = v; __syncthreads();
#pragma unroll
        for (int s = 64; s; s >>= 1) {
            if (c < s) red[t] = fmaxf(red[t], red[t + s]);
            __syncthreads();
        }
        float mx = red[local * 128];
        __syncthreads();
        float ex = expf(v - mx);
        red[t] = ex; __syncthreads();
#pragma unroll
        for (int s = 64; s; s >>= 1) {
            if (c < s) red[t] += red[t + s];
            __syncthreads();
        }
        out[(size_t)i * CHN + c] = ex / red[local * 128];
    }
}

__global__ __launch_bounds__(256) void k_agg_plain(
    const float* __restrict__ in, float* __restrict__ out)
{
    int t = threadIdx.x;
    int local = t >> 7;
    int c = t & 127;
    int i = blockIdx.x * 2 + local;
    float acc = 0.f;
    int e = g_off[i];
    int e1 = e + g_deg[i];
    for (; e + 4 <= e1; e += 4) {
        int s0 = g_srcbuf[e], s1 = g_srcbuf[e + 1], s2 = g_srcbuf[e + 2], s3 = g_srcbuf[e + 3];
        acc += in[(size_t)s0 * CH + c] + in[(size_t)s1 * CH + c]
             + in[(size_t)s2 * CH + c] + in[(size_t)s3 * CH + c];
    }
    for (; e < e1; e++) acc += in[(size_t)g_srcbuf[e] * CH + c];
    out[(size_t)i * CH + c] = acc;
}

// ---------------- batch-norm stats + apply (fin inlined) ----------------
__global__ __launch_bounds__(128) void k_bnstats(const float* __restrict__ x, int nrows) {
    int c = threadIdx.x;
    float s = 0.f, q = 0.f;
    for (int r = blockIdx.x; r < nrows; r += gridDim.x) {
        float v = x[(long long)r * CH + c];
        s += v; q += v * v;
    }
    atomicAdd(&g_sum[c], s);
    atomicAdd(&g_ss[c], q);
}

__global__ __launch_bounds__(256) void k_bnapply4(
    const float4* __restrict__ x, const float4* __restrict__ res, float4* __restrict__ out,
    int n4, const float* __restrict__ gw, const float* __restrict__ be, float inv_n)
{
    __shared__ float sA[128], sB[128];
    int t = threadIdx.x;
    if (t < 128) {
        float m = g_sum[t] * inv_n;
        float v = g_ss[t] * inv_n - m * m;
        float sc = gw[t] * rsqrtf(v + 1e-5f);
        sA[t] = sc;
        sB[t] = be[t] - sc * m;
    }
    __syncthreads();
    int i = blockIdx.x * 256 + t;
    if (i >= n4) return;
    int c0 = (i & 31) << 2;
    float4 xv = x[i];
    float4 o;
    float y;
    y = sA[c0 + 0] * xv.x + sB[c0 + 0]; o.x = y / (1.f + __expf(-y));
    y = sA[c0 + 1] * xv.y + sB[c0 + 1]; o.y = y / (1.f + __expf(-y));
    y = sA[c0 + 2] * xv.z + sB[c0 + 2]; o.z = y / (1.f + __expf(-y));
    y = sA[c0 + 3] * xv.w + sB[c0 + 3]; o.w = y / (1.f + __expf(-y));
    if (res) {
        float4 r = res[i];
        o.x += r.x; o.y += r.y; o.z += r.z; o.w += r.w;
    }
    out[i] = o;
}

// ---------------- partial reduce + dinv2 + An (per batch) ----------------
__global__ __launch_bounds__(256) void k_reduce_an() {
    int b = blockIdx.x;
    int t = threadIdx.x;
    const int PS = NB * CH * CH;
    const int BO = b * CH * CH;
    __shared__ float sd[128];
    for (int idx = t; idx < CH * CH; idx += 256) {
        float s = g_xpart[0 * PS + BO + idx] + g_xpart[1 * PS + BO + idx]
                + g_xpart[2 * PS + BO + idx] + g_xpart[3 * PS + BO + idx];
        g_x2[BO + idx] = s;
    }
    int w = t >> 5, lane = t & 31;
    for (int r = w; r < 128; r += 8) {
        float rsum = 0.f;
#pragma unroll
        for (int q = 0; q < 4; q++) {
            int idx = r * 128 + lane + q * 32;
            float s = g_apart[0 * PS + BO + idx] + g_apart[1 * PS + BO + idx]
                    + g_apart[2 * PS + BO + idx] + g_apart[3 * PS + BO + idx];
            g_A2[BO + idx] = s;
            rsum += s;
        }
#pragma unroll
        for (int o = 16; o; o >>= 1) rsum += __shfl_down_sync(0xffffffffu, rsum, o);
        if (lane == 0) sd[r] = rsqrtf(rsum + 1.0f);
    }
    __syncthreads();
    for (int idx = t; idx < CH * CH; idx += 256) {
        int i = idx >> 7, j = idx & 127;
        float v = g_A2[BO + idx] + (i == j ? 1.f : 0.f);
        g_An[BO + idx] = sd[i] * v * sd[j];
    }
}

// ---------------- pooled column-mean + linear head + log_softmax ----------------
__global__ __launch_bounds__(128) void k_head(
    const float* __restrict__ wl, const float* __restrict__ bl, float* __restrict__ out, int out_size)
{
    int b = blockIdx.x;
    int t = threadIdx.x;
    __shared__ float gv[128];
    __shared__ float lg[10];
    __shared__ float s_lse;
    float s = 0.f;
    for (int n = 0; n < 128; n++) s += g_h2[((long long)b * 128 + n) * 128 + t];
    gv[t] = s * (1.f / 32.f);
    __syncthreads();
    if (t < 10) {
        float a = bl[t];
        for (int k = 0; k < 128; k++) a += gv[k] * wl[k * 10 + t];
        lg[t] = a;
    }
    __syncthreads();
    if (t == 0) {
        float mx = -1e30f;
        for (int j = 0; j < 10; j++) mx = fmaxf(mx, lg[j]);
        float se = 0.f;
        for (int j = 0; j < 10; j++) se += expf(lg[j] - mx);
        s_lse = mx + logf(se);
    }
    __syncthreads();
    if (t < 10) {
        int o = b * 10 + t;
        if (o < out_size) out[o] = lg[t] - s_lse;
    }
}

// ---------------- host orchestration ----------------
extern "C" void kernel_launch(void* const* d_in, const int* in_sizes, int n_in,
                              void* d_out, int out_size) {
    const float* x    = (const float*)d_in[0];
    const int*   ei   = (const int*)  d_in[1];
    const float* w1a  = (const float*)d_in[4];
    const float* b1a  = (const float*)d_in[5];
    const float* g1a  = (const float*)d_in[6];
    const float* be1a = (const float*)d_in[7];
    const float* w1b  = (const float*)d_in[8];
    const float* b1b  = (const float*)d_in[9];
    const float* g1b  = (const float*)d_in[10];
    const float* be1b = (const float*)d_in[11];
    const float* wp1  = (const float*)d_in[12];
    const float* bp1  = (const float*)d_in[13];
    const float* w2a  = (const float*)d_in[14];
    const float* b2a  = (const float*)d_in[15];
    const float* g2a  = (const float*)d_in[16];
    const float* be2a = (const float*)d_in[17];
    const float* w2b  = (const float*)d_in[18];
    const float* b2b  = (const float*)d_in[19];
    const float* g2b  = (const float*)d_in[20];
    const float* be2b = (const float*)d_in[21];
    // d_in[22]=wp2, d_in[23]=bp2 dead (softmax rows sum to 1)
    const float* wl   = (const float*)d_in[24];
    const float* bl   = (const float*)d_in[25];
    float* outp = (float*)d_out;
    (void)n_in; (void)in_sizes;

    float *p_aggx, *p_lin, *p_y, *p_h, *p_s, *p_t;
    float *p_xpart, *p_apart, *p_x2, *p_An, *p_h2, *p_tmp2, *p_y2;
    cudaGetSymbolAddress((void**)&p_aggx,  g_aggx);
    cudaGetSymbolAddress((void**)&p_lin,   g_lin);
    cudaGetSymbolAddress((void**)&p_y,     g_y);
    cudaGetSymbolAddress((void**)&p_h,     g_h);
    cudaGetSymbolAddress((void**)&p_s,     g_s);
    cudaGetSymbolAddress((void**)&p_t,     g_t);
    cudaGetSymbolAddress((void**)&p_xpart, g_xpart);
    cudaGetSymbolAddress((void**)&p_apart, g_apart);
    cudaGetSymbolAddress((void**)&p_x2,    g_x2);
    cudaGetSymbolAddress((void**)&p_An,    g_An);
    cudaGetSymbolAddress((void**)&p_h2,    g_h2);
    cudaGetSymbolAddress((void**)&p_tmp2,  g_tmp2);
    cudaGetSymbolAddress((void**)&p_y2,    g_y2);

    const int NC = NNODES * CH;     // 4194304
    const int S2 = NB * CH * CH;    // 524288

    // --- graph structure ---
    k_zero_deg<<<NNODES / 256, 256>>>();
    k_deg  <<<NEDGES / 256, 256>>>(ei);
    k_alloc<<<NNODES / 1024, 1024>>>();
    k_fill <<<NEDGES / 256, 256>>>(ei);

    // --- stack 1, layer a: agg(x) first (64ch), then GEMM 64->128 with bias ---
    k_agg_gcn<64, false, false><<<NNODES / 4, 256>>>(x, nullptr, p_aggx);
    k_gemm<false><<<dim3(256, 1, 1), 256>>>(p_aggx, w1a, b1a, p_y, 64, 64, 0, 0, 0, 0, 1);
    k_bnstats<<<256, 128>>>(p_y, NNODES);
    k_bnapply4<<<NC / 1024, 256>>>((const float4*)p_y, nullptr, (float4*)p_h, NC / 4, g1a, be1a, 1.f / NNODES);

    // --- stack 1, layer b (residual) ---
    k_gemm<false><<<dim3(256, 1, 1), 256>>>(p_h, w1b, nullptr, p_lin, 128, 128, 0, 0, 0, 0, 0);
    k_agg_gcn<128, false, true><<<NNODES / 2, 256>>>(p_lin, b1b, p_y);
    k_bnstats<<<256, 128>>>(p_y, NNODES);
    k_bnapply4<<<NC / 1024, 256>>>((const float4*)p_y, (const float4*)p_h, (float4*)p_h, NC / 4, g1b, be1b, 1.f / NNODES);

    // --- pooling 1: s = softmax(gcn(h, wp1)) fused; t = A s ---
    k_gemm<false><<<dim3(256, 1, 1), 256>>>(p_h, wp1, nullptr, p_lin, 128, 128, 0, 0, 0, 0, 0);
    k_agg_gcn<128, true, false><<<NNODES / 2, 256>>>(p_lin, bp1, p_s);
    k_agg_plain<<<NNODES / 2, 256>>>(p_s, p_t);

    // --- pooled einsums: K-split x4 into partial buffers (no atomics) ---
    k_gemm<true><<<dim3(1, 4, NB), 256>>>(p_s, p_h, nullptr, p_xpart, 128, 256,
                                          (long long)NPG * CH, (long long)NPG * CH,
                                          (long long)CH * CH, (long long)NB * CH * CH, 0);
    k_gemm<true><<<dim3(1, 4, NB), 256>>>(p_s, p_t, nullptr, p_apart, 128, 256,
                                          (long long)NPG * CH, (long long)NPG * CH,
                                          (long long)CH * CH, (long long)NB * CH * CH, 0);
    k_reduce_an<<<NB, 256>>>();

    // --- stack 2, layer a ---
    k_gemm64<<<dim3(64, 2, 1), 256>>>(p_x2, w2a, nullptr, p_tmp2, 128, 0, 0, 0, 0);
    k_gemm64<<<dim3(2, 2, NB), 256>>>(p_An, p_tmp2, b2a, p_y2, 128, 16384, 16384, 16384, 1);
    k_bnstats<<<64, 128>>>(p_y2, NB * CH);
    k_bnapply4<<<S2 / 1024, 256>>>((const float4*)p_y2, nullptr, (float4*)p_h2, S2 / 4, g2a, be2a, 1.f / (NB * CH));

    // --- stack 2, layer b (residual) ---
    k_gemm64<<<dim3(64, 2, 1), 256>>>(p_h2, w2b, nullptr, p_tmp2, 128, 0, 0, 0, 0);
    k_gemm64<<<dim3(2, 2, NB), 256>>>(p_An, p_tmp2, b2b, p_y2, 128, 16384, 16384, 16384, 1);
    k_bnstats<<<64, 128>>>(p_y2, NB * CH);
    k_bnapply4<<<S2 / 1024, 256>>>((const float4*)p_y2, (const float4*)p_h2, (float4*)p_h2, S2 / 4, g2b, be2b, 1.f / (NB * CH));

    // --- head ---
    k_head<<<NB, 128>>>(wl, bl, outp, out_size);

    if (out_size > NB * 10) {
        int tail = out_size - NB * 10;
        k_zero_f<<<(tail + 255) / 256, 256>>>(outp + NB * 10, tail);
    }
}